// round 3
// baseline (speedup 1.0000x reference)
#include <cuda_runtime.h>
#include <math.h>

#define BB 4
#define SS 2048
#define DM 768
#define NH 12
#define DK 64
#define NT (BB*SS)          // 8192 tokens
#define BHN (BB*NH)         // 48

// Scratch (device globals: no allocation allowed)
__device__ float g_Q[(size_t)BHN*SS*DK];   // [B,H,S,dk]
__device__ float g_K[(size_t)BHN*SS*DK];
__device__ float g_V[(size_t)BHN*SS*DK];
__device__ float g_AO[(size_t)NT*DM];      // attn_out in [B,S,D]

// ---------------------------------------------------------------------------
// SGEMM 128x128 tile, 256 threads, 8x8 per thread, K-step 8.
// C = A[NT,DM] @ W[DM,DM] + bias.  HEADSPLIT: write [B,H,S,dk] layout.
// ---------------------------------------------------------------------------
template<bool HEADSPLIT>
__global__ __launch_bounds__(256) void sgemm_proj(
    const float* __restrict__ A, const float* __restrict__ W,
    const float* __restrict__ bias, float* __restrict__ C)
{
    __shared__ float As[8][128];
    __shared__ float Bs[8][128];
    const int t = threadIdx.x;
    const int rowBase = blockIdx.y * 128;
    const int colBase = blockIdx.x * 128;
    const int ty = t >> 4, tx = t & 15;

    float acc[8][8];
    #pragma unroll
    for (int i = 0; i < 8; i++)
        #pragma unroll
        for (int j = 0; j < 8; j++) acc[i][j] = 0.f;

    const int arow = t >> 1, ac4 = t & 1;    // A tile: 128 rows x 2 float4
    const int brow = t >> 5, bc4 = t & 31;   // B tile: 8 rows x 32 float4
    const float* Ap = A + (size_t)(rowBase + arow) * DM + ac4 * 4;
    const float* Bp = W + (size_t)brow * DM + colBase + bc4 * 4;

    for (int kt = 0; kt < DM; kt += 8) {
        float4 av = *(const float4*)(Ap + kt);
        float4 bv = *(const float4*)(Bp + (size_t)kt * DM);
        As[ac4*4+0][arow] = av.x;
        As[ac4*4+1][arow] = av.y;
        As[ac4*4+2][arow] = av.z;
        As[ac4*4+3][arow] = av.w;
        *(float4*)&Bs[brow][bc4*4] = bv;
        __syncthreads();
        #pragma unroll
        for (int k = 0; k < 8; k++) {
            float a[8], b[8];
            *(float4*)(a)   = *(const float4*)&As[k][ty*8];
            *(float4*)(a+4) = *(const float4*)&As[k][ty*8+4];
            *(float4*)(b)   = *(const float4*)&Bs[k][tx*8];
            *(float4*)(b+4) = *(const float4*)&Bs[k][tx*8+4];
            #pragma unroll
            for (int i = 0; i < 8; i++)
                #pragma unroll
                for (int j = 0; j < 8; j++) acc[i][j] += a[i] * b[j];
        }
        __syncthreads();
    }

    #pragma unroll
    for (int i = 0; i < 8; i++) {
        const int r = rowBase + ty*8 + i;
        const int bidx = r / SS, s = r % SS;
        #pragma unroll
        for (int jj = 0; jj < 8; jj += 4) {
            const int c = colBase + tx*8 + jj;
            float4 bb = *(const float4*)&bias[c];
            float4 v;
            v.x = acc[i][jj+0] + bb.x;
            v.y = acc[i][jj+1] + bb.y;
            v.z = acc[i][jj+2] + bb.z;
            v.w = acc[i][jj+3] + bb.w;
            if (HEADSPLIT) {
                const int h = c / DK, kk = c % DK;
                *(float4*)&C[(((size_t)bidx*NH + h)*SS + s)*DK + kk] = v;
            } else {
                *(float4*)&C[(size_t)r*DM + c] = v;
            }
        }
    }
}

// ---------------------------------------------------------------------------
// scores[bh][q][k] = scale * dot(Q[bh][q,:], K[bh][k,:])  (M=N=2048, K=64)
// ---------------------------------------------------------------------------
__global__ __launch_bounds__(256) void scores_kernel(
    const float* __restrict__ Q, const float* __restrict__ Kt,
    float* __restrict__ attn)
{
    const int bh = blockIdx.z;
    const float* Qp = Q  + (size_t)bh * SS * DK;
    const float* Kp = Kt + (size_t)bh * SS * DK;
    float* Cp = attn + (size_t)bh * SS * SS;

    __shared__ float As[8][128];
    __shared__ float Bs[8][128];
    const int t = threadIdx.x;
    const int qBase = blockIdx.y * 128;
    const int kBase = blockIdx.x * 128;
    const int ty = t >> 4, tx = t & 15;

    float acc[8][8];
    #pragma unroll
    for (int i = 0; i < 8; i++)
        #pragma unroll
        for (int j = 0; j < 8; j++) acc[i][j] = 0.f;

    const int lrow = t >> 1, lc4 = t & 1;
    const float* Ap = Qp + (size_t)(qBase + lrow) * DK + lc4 * 4;
    const float* Bp = Kp + (size_t)(kBase + lrow) * DK + lc4 * 4;

    #pragma unroll
    for (int kt = 0; kt < DK; kt += 8) {
        float4 av = *(const float4*)(Ap + kt);
        float4 bv = *(const float4*)(Bp + kt);
        As[lc4*4+0][lrow] = av.x; As[lc4*4+1][lrow] = av.y;
        As[lc4*4+2][lrow] = av.z; As[lc4*4+3][lrow] = av.w;
        Bs[lc4*4+0][lrow] = bv.x; Bs[lc4*4+1][lrow] = bv.y;
        Bs[lc4*4+2][lrow] = bv.z; Bs[lc4*4+3][lrow] = bv.w;
        __syncthreads();
        #pragma unroll
        for (int k = 0; k < 8; k++) {
            float a[8], b[8];
            *(float4*)(a)   = *(const float4*)&As[k][ty*8];
            *(float4*)(a+4) = *(const float4*)&As[k][ty*8+4];
            *(float4*)(b)   = *(const float4*)&Bs[k][tx*8];
            *(float4*)(b+4) = *(const float4*)&Bs[k][tx*8+4];
            #pragma unroll
            for (int i = 0; i < 8; i++)
                #pragma unroll
                for (int j = 0; j < 8; j++) acc[i][j] += a[i] * b[j];
        }
        __syncthreads();
    }

    const float scale = 0.125f;  // 1/sqrt(64)
    #pragma unroll
    for (int i = 0; i < 8; i++) {
        const int qi = qBase + ty*8 + i;
        #pragma unroll
        for (int jj = 0; jj < 8; jj += 4) {
            float4 v;
            v.x = acc[i][jj+0] * scale;
            v.y = acc[i][jj+1] * scale;
            v.z = acc[i][jj+2] * scale;
            v.w = acc[i][jj+3] * scale;
            *(float4*)&Cp[(size_t)qi * SS + kBase + tx*8 + jj] = v;
        }
    }
}

// ---------------------------------------------------------------------------
// In-place row softmax over the attn region. 1 block (256 thr) per row of 2048.
// ---------------------------------------------------------------------------
__global__ __launch_bounds__(256) void softmax_kernel(float* __restrict__ attn)
{
    const size_t row = blockIdx.x;
    float* p = attn + row * (size_t)SS;
    const int t = threadIdx.x;

    float4 v0 = ((const float4*)p)[t];
    float4 v1 = ((const float4*)p)[t + 256];

    __shared__ float redm[8];
    __shared__ float reds[8];

    float m = fmaxf(fmaxf(fmaxf(v0.x, v0.y), fmaxf(v0.z, v0.w)),
                    fmaxf(fmaxf(v1.x, v1.y), fmaxf(v1.z, v1.w)));
    #pragma unroll
    for (int o = 16; o > 0; o >>= 1) m = fmaxf(m, __shfl_xor_sync(0xffffffffu, m, o));
    if ((t & 31) == 0) redm[t >> 5] = m;
    __syncthreads();
    float bm = redm[0];
    #pragma unroll
    for (int w = 1; w < 8; w++) bm = fmaxf(bm, redm[w]);

    v0.x = __expf(v0.x - bm); v0.y = __expf(v0.y - bm);
    v0.z = __expf(v0.z - bm); v0.w = __expf(v0.w - bm);
    v1.x = __expf(v1.x - bm); v1.y = __expf(v1.y - bm);
    v1.z = __expf(v1.z - bm); v1.w = __expf(v1.w - bm);

    float s = v0.x + v0.y + v0.z + v0.w + v1.x + v1.y + v1.z + v1.w;
    #pragma unroll
    for (int o = 16; o > 0; o >>= 1) s += __shfl_xor_sync(0xffffffffu, s, o);
    if ((t & 31) == 0) reds[t >> 5] = s;
    __syncthreads();
    float bs = reds[0];
    #pragma unroll
    for (int w = 1; w < 8; w++) bs += reds[w];

    const float inv = 1.0f / bs;
    v0.x *= inv; v0.y *= inv; v0.z *= inv; v0.w *= inv;
    v1.x *= inv; v1.y *= inv; v1.z *= inv; v1.w *= inv;
    ((float4*)p)[t]       = v0;
    ((float4*)p)[t + 256] = v1;
}

// ---------------------------------------------------------------------------
// attn_out = P @ V per (b,h).  M=2048, N=64, K=2048.
// Tile 128x64, 256 threads, 8x4 per thread, K-step 16.
// Writes [B,S,D] layout into g_AO.
// ---------------------------------------------------------------------------
__global__ __launch_bounds__(256) void pv_kernel(
    const float* __restrict__ P, const float* __restrict__ V,
    float* __restrict__ AO)
{
    const int bh = blockIdx.z;
    const int b = bh / NH, h = bh % NH;
    const float* Pp = P + (size_t)bh * SS * SS;
    const float* Vp = V + (size_t)bh * SS * DK;

    __shared__ float As[16][128];
    __shared__ float Bs[16][64];
    const int t = threadIdx.x;
    const int rowBase = blockIdx.y * 128;
    const int ty = t >> 4, tx = t & 15;

    float acc[8][4];
    #pragma unroll
    for (int i = 0; i < 8; i++)
        #pragma unroll
        for (int j = 0; j < 4; j++) acc[i][j] = 0.f;

    const int ar0 = t >> 2, ac0 = t & 3;     // A tile: 128 rows x 4 float4 (x2)
    const int brow = t >> 4, bc4 = t & 15;   // B tile: 16 rows x 16 float4

    for (int kt = 0; kt < SS; kt += 16) {
        float4 a0 = *(const float4*)(Pp + (size_t)(rowBase + ar0)      * SS + kt + ac0*4);
        float4 a1 = *(const float4*)(Pp + (size_t)(rowBase + ar0 + 64) * SS + kt + ac0*4);
        float4 bv = *(const float4*)(Vp + (size_t)(kt + brow) * DK + bc4*4);
        As[ac0*4+0][ar0] = a0.x; As[ac0*4+1][ar0] = a0.y;
        As[ac0*4+2][ar0] = a0.z; As[ac0*4+3][ar0] = a0.w;
        As[ac0*4+0][ar0+64] = a1.x; As[ac0*4+1][ar0+64] = a1.y;
        As[ac0*4+2][ar0+64] = a1.z; As[ac0*4+3][ar0+64] = a1.w;
        *(float4*)&Bs[brow][bc4*4] = bv;
        __syncthreads();
        #pragma unroll
        for (int k = 0; k < 16; k++) {
            float a[8], bb[4];
            *(float4*)(a)   = *(const float4*)&As[k][ty*8];
            *(float4*)(a+4) = *(const float4*)&As[k][ty*8+4];
            *(float4*)(bb)  = *(const float4*)&Bs[k][tx*4];
            #pragma unroll
            for (int i = 0; i < 8; i++)
                #pragma unroll
                for (int j = 0; j < 4; j++) acc[i][j] += a[i] * bb[j];
        }
        __syncthreads();
    }

    #pragma unroll
    for (int i = 0; i < 8; i++) {
        const int s = rowBase + ty*8 + i;
        float4 v = { acc[i][0], acc[i][1], acc[i][2], acc[i][3] };
        *(float4*)&AO[((size_t)b*SS + s)*DM + h*DK + tx*4] = v;
    }
}

// ---------------------------------------------------------------------------
extern "C" void kernel_launch(void* const* d_in, const int* in_sizes, int n_in,
                              void* d_out, int out_size)
{
    (void)in_sizes; (void)n_in; (void)out_size;
    const float* q  = (const float*)d_in[0];
    const float* k  = (const float*)d_in[1];
    const float* v  = (const float*)d_in[2];
    const float* Wq = (const float*)d_in[3];
    const float* bq = (const float*)d_in[4];
    const float* Wk = (const float*)d_in[5];
    const float* bk = (const float*)d_in[6];
    const float* Wv = (const float*)d_in[7];
    const float* bv = (const float*)d_in[8];
    const float* Wo = (const float*)d_in[9];
    const float* bo = (const float*)d_in[10];

    float* out  = (float*)d_out;
    float* attn = out + (size_t)NT * DM;   // attn_weights region

    float *pQ, *pK, *pV, *pAO;
    cudaGetSymbolAddress((void**)&pQ,  g_Q);
    cudaGetSymbolAddress((void**)&pK,  g_K);
    cudaGetSymbolAddress((void**)&pV,  g_V);
    cudaGetSymbolAddress((void**)&pAO, g_AO);

    dim3 blk(256);
    dim3 gProj(DM / 128, NT / 128);            // 6 x 64
    sgemm_proj<true><<<gProj, blk>>>(q, Wq, bq, pQ);
    sgemm_proj<true><<<gProj, blk>>>(k, Wk, bk, pK);
    sgemm_proj<true><<<gProj, blk>>>(v, Wv, bv, pV);

    dim3 gScores(SS / 128, SS / 128, BHN);     // 16 x 16 x 48
    scores_kernel<<<gScores, blk>>>(pQ, pK, attn);

    softmax_kernel<<<(unsigned)((size_t)BHN * SS), blk>>>(attn);

    dim3 gPV(1, SS / 128, BHN);                // 1 x 16 x 48
    pv_kernel<<<gPV, blk>>>(attn, pV, pAO);

    sgemm_proj<false><<<gProj, blk>>>(pAO, Wo, bo, out);
}